// round 6
// baseline (speedup 1.0000x reference)
#include <cuda_runtime.h>
#include <math.h>

#define BT   64
#define NCTA 128
#define NTHR 256
#define TH   20
#define LP   30
#define DTC  0.1f
#define D2C  0.005f

typedef unsigned long long ull;

struct SM {
    ulonglong2 Wp[3][64][32];   // 96KB: per (l, k[0..31 x | 32..63 h], dg): floats {Wi,Wf,Wg,Wo} -> .x={i,f} .y={g,o}
    float  Hd[3][32][128];      // 48KB: h duplicated per batch: [l][k][2b]==[2b+1]
    float  xd[32][128];         // 16KB: x (input act / c of prev layer) duplicated
    float  XPd[24][128];        // 12KB: Kalman state duplicated
    float  Zs[2][TH][BT];       // 10KB
    float  pred[4][BT];         // 1KB
    float4 bsum2[3][32];        // {bi,bf,bg,bo} per (l,d)
    float2 Winp[24][16];        // {Win[dg][k], Win[dg+16][k]}
    float2 Winb2[16];
    float  WoutT[32][4];
    float  Woutb[4];
};

__device__ __forceinline__ float tanha(float x) {
    float y; asm("tanh.approx.f32 %0, %1;" : "=f"(y) : "f"(x)); return y;
}
__device__ __forceinline__ float sigm(float z) {
    return fmaf(tanha(0.5f * z), 0.5f, 0.5f);
}
__device__ __forceinline__ void ffma2(ull& a, ull w, ull x) {
    asm("fma.rn.f32x2 %0, %1, %2, %0;" : "+l"(a) : "l"(w), "l"(x));
}
__device__ __forceinline__ float2 u2f2(ull v) {
    float2 r; asm("mov.b64 {%0, %1}, %2;" : "=f"(r.x), "=f"(r.y) : "l"(v)); return r;
}
__device__ __forceinline__ ull f2u2(float lo, float hi) {
    ull r; asm("mov.b64 %0, {%1, %2};" : "=l"(r) : "f"(lo), "f"(hi)); return r;
}

__device__ __forceinline__ void pack_weights(SM& s, int tid,
        const float* __restrict__ Wih, const float* __restrict__ Whh,
        const float* __restrict__ bih, const float* __restrict__ bhh) {
    for (int i = tid; i < 3 * 64 * 32; i += NTHR) {
        int d = i & 31, kk = (i >> 5) & 63, l = i >> 11;
        const float* W = (kk < 32) ? Wih : Whh;
        int k = kk & 31;
        int base = l * 4096 + d * 32 + k;
        float4 v;
        v.x = W[base];
        v.y = W[base + 1024];
        v.z = W[base + 2048];
        v.w = W[base + 3072];
        *reinterpret_cast<float4*>(&s.Wp[l][kk][d]) = v;
    }
    for (int i = tid; i < 96; i += NTHR) {
        int l = i >> 5, d = i & 31;
        int b = l * 128 + d;
        float4 v;
        v.x = bih[b]      + bhh[b];
        v.y = bih[b + 32] + bhh[b + 32];
        v.z = bih[b + 64] + bhh[b + 64];
        v.w = bih[b + 96] + bhh[b + 96];
        s.bsum2[l][d] = v;
    }
}

// Kalman predict with Q[i][j] = g_i * g_j
__device__ __forceinline__ void kpred_f(float X[3], float P[9],
                                        float g0, float g1, float g2) {
    X[0] = X[0] + DTC * X[1] + D2C * X[2];
    X[1] = X[1] + DTC * X[2];
    float A[9];
#pragma unroll
    for (int j = 0; j < 3; j++) {
        A[0 * 3 + j] = P[0 * 3 + j] + DTC * P[1 * 3 + j] + D2C * P[2 * 3 + j];
        A[1 * 3 + j] = P[1 * 3 + j] + DTC * P[2 * 3 + j];
        A[2 * 3 + j] = P[2 * 3 + j];
    }
#pragma unroll
    for (int i = 0; i < 3; i++) {
        float qi = (i == 0) ? g0 : ((i == 1) ? g1 : g2);
        P[i * 3 + 0] = A[i * 3 + 0] + DTC * A[i * 3 + 1] + D2C * A[i * 3 + 2] + qi * g0;
        P[i * 3 + 1] = A[i * 3 + 1] + DTC * A[i * 3 + 2] + qi * g1;
        P[i * 3 + 2] = A[i * 3 + 2] + qi * g2;
    }
}

__device__ __forceinline__ void kupd_f(float X[3], float P[9], float z, float R) {
    float y = z - X[0];
    float S = P[0] + R;
    float inv = 1.0f / S;
    float K0 = P[0] * inv, K1 = P[3] * inv, K2 = P[6] * inv;
    X[0] += y * K0; X[1] += y * K1; X[2] += y * K2;
    float r0 = P[0], r1 = P[1], r2 = P[2];
    P[0] -= K0 * r0; P[1] -= K0 * r1; P[2] -= K0 * r2;
    P[3] -= K1 * r0; P[4] -= K1 * r1; P[5] -= K1 * r2;
    P[6] -= K2 * r0; P[7] -= K2 * r1; P[8] -= K2 * r2;
}

// input layer + 3 LSTM layers; leaves c[2] (dup) in s.xd. Warp-local only.
__device__ __forceinline__ void run_stack(SM& s, int dg, int cb, float Creg[3][2][4]) {
    // ---- input layer: x = tanh(XP @ Win^T + b), accs paired over (dg, dg+16) ----
    {
        float2 wb = s.Winb2[dg];
        ull acc[4];
        ull binit = f2u2(wb.x, wb.y);
#pragma unroll
        for (int b = 0; b < 4; b++) acc[b] = binit;
#pragma unroll 6
        for (int k = 0; k < 24; k++) {
            ulonglong2 X01 = *reinterpret_cast<const ulonglong2*>(&s.XPd[k][cb]);
            ulonglong2 X23 = *reinterpret_cast<const ulonglong2*>(&s.XPd[k][cb + 4]);
            ull w = *reinterpret_cast<const ull*>(&s.Winp[k][dg]);
            ffma2(acc[0], w, X01.x); ffma2(acc[1], w, X01.y);
            ffma2(acc[2], w, X23.x); ffma2(acc[3], w, X23.y);
        }
        float t0[4], t1[4];
#pragma unroll
        for (int b = 0; b < 4; b++) {
            float2 v = u2f2(acc[b]);
            t0[b] = tanha(v.x); t1[b] = tanha(v.y);
        }
        float4 a01, a23;
        a01.x = t0[0]; a01.y = t0[0]; a01.z = t0[1]; a01.w = t0[1];
        a23.x = t0[2]; a23.y = t0[2]; a23.z = t0[3]; a23.w = t0[3];
        *reinterpret_cast<float4*>(&s.xd[dg][cb])     = a01;
        *reinterpret_cast<float4*>(&s.xd[dg][cb + 4]) = a23;
        a01.x = t1[0]; a01.y = t1[0]; a01.z = t1[1]; a01.w = t1[1];
        a23.x = t1[2]; a23.y = t1[2]; a23.z = t1[3]; a23.w = t1[3];
        *reinterpret_cast<float4*>(&s.xd[dg + 16][cb])     = a01;
        *reinterpret_cast<float4*>(&s.xd[dg + 16][cb + 4]) = a23;
    }
    __syncwarp();

    // ---- 3 LSTM layers: accs paired over gates {i,f} and {g,o} ----
#pragma unroll 1
    for (int l = 0; l < 3; l++) {
        float4 b0 = s.bsum2[l][dg];
        float4 b1 = s.bsum2[l][dg + 16];
        ull aif[2][4], ago[2][4];
        {
            ull i0 = f2u2(b0.x, b0.y), g0 = f2u2(b0.z, b0.w);
            ull i1 = f2u2(b1.x, b1.y), g1 = f2u2(b1.z, b1.w);
#pragma unroll
            for (int b = 0; b < 4; b++) {
                aif[0][b] = i0; ago[0][b] = g0;
                aif[1][b] = i1; ago[1][b] = g1;
            }
        }
        const ulonglong2* __restrict__ wl = &s.Wp[l][0][0];
        const float* __restrict__ hl = &s.Hd[l][0][0];
        // x part
#pragma unroll 8
        for (int k = 0; k < 32; k++) {
            ulonglong2 X01 = *reinterpret_cast<const ulonglong2*>(&s.xd[k][cb]);
            ulonglong2 X23 = *reinterpret_cast<const ulonglong2*>(&s.xd[k][cb + 4]);
            ulonglong2 w0 = wl[k * 32 + dg];
            ulonglong2 w1 = wl[k * 32 + dg + 16];
            ffma2(aif[0][0], w0.x, X01.x); ffma2(ago[0][0], w0.y, X01.x);
            ffma2(aif[0][1], w0.x, X01.y); ffma2(ago[0][1], w0.y, X01.y);
            ffma2(aif[0][2], w0.x, X23.x); ffma2(ago[0][2], w0.y, X23.x);
            ffma2(aif[0][3], w0.x, X23.y); ffma2(ago[0][3], w0.y, X23.y);
            ffma2(aif[1][0], w1.x, X01.x); ffma2(ago[1][0], w1.y, X01.x);
            ffma2(aif[1][1], w1.x, X01.y); ffma2(ago[1][1], w1.y, X01.y);
            ffma2(aif[1][2], w1.x, X23.x); ffma2(ago[1][2], w1.y, X23.x);
            ffma2(aif[1][3], w1.x, X23.y); ffma2(ago[1][3], w1.y, X23.y);
        }
        // h part
#pragma unroll 8
        for (int k = 0; k < 32; k++) {
            ulonglong2 H01 = *reinterpret_cast<const ulonglong2*>(&hl[k * 128 + cb]);
            ulonglong2 H23 = *reinterpret_cast<const ulonglong2*>(&hl[k * 128 + cb + 4]);
            ulonglong2 w0 = wl[(32 + k) * 32 + dg];
            ulonglong2 w1 = wl[(32 + k) * 32 + dg + 16];
            ffma2(aif[0][0], w0.x, H01.x); ffma2(ago[0][0], w0.y, H01.x);
            ffma2(aif[0][1], w0.x, H01.y); ffma2(ago[0][1], w0.y, H01.y);
            ffma2(aif[0][2], w0.x, H23.x); ffma2(ago[0][2], w0.y, H23.x);
            ffma2(aif[0][3], w0.x, H23.y); ffma2(ago[0][3], w0.y, H23.y);
            ffma2(aif[1][0], w1.x, H01.x); ffma2(ago[1][0], w1.y, H01.x);
            ffma2(aif[1][1], w1.x, H01.y); ffma2(ago[1][1], w1.y, H01.y);
            ffma2(aif[1][2], w1.x, H23.x); ffma2(ago[1][2], w1.y, H23.x);
            ffma2(aif[1][3], w1.x, H23.y); ffma2(ago[1][3], w1.y, H23.y);
        }
        __syncwarp();   // all lanes done reading xd / Hd[l] before overwrite
#pragma unroll
        for (int dp = 0; dp < 2; dp++) {
            int d = dg + 16 * dp;
            float cn[4], hn[4];
#pragma unroll
            for (int b = 0; b < 4; b++) {
                float2 vif = u2f2(aif[dp][b]);
                float2 vgo = u2f2(ago[dp][b]);
                float c = fmaf(sigm(vif.y), Creg[l][dp][b], sigm(vif.x) * tanha(vgo.x));
                float h = sigm(vgo.y) * tanha(c);
                Creg[l][dp][b] = c;
                cn[b] = c; hn[b] = h;
            }
            float4 c01, c23, h01, h23;
            c01.x = cn[0]; c01.y = cn[0]; c01.z = cn[1]; c01.w = cn[1];
            c23.x = cn[2]; c23.y = cn[2]; c23.z = cn[3]; c23.w = cn[3];
            h01.x = hn[0]; h01.y = hn[0]; h01.z = hn[1]; h01.w = hn[1];
            h23.x = hn[2]; h23.y = hn[2]; h23.z = hn[3]; h23.w = hn[3];
            *reinterpret_cast<float4*>(&s.xd[d][cb])            = c01;
            *reinterpret_cast<float4*>(&s.xd[d][cb + 4])        = c23;
            *reinterpret_cast<float4*>(&s.Hd[l][d][cb])         = h01;
            *reinterpret_cast<float4*>(&s.Hd[l][d][cb + 4])     = h23;
        }
        __syncwarp();
    }
}

__global__ void __launch_bounds__(NTHR, 1)
kalman_lstm_kernel(const float* __restrict__ hist,
                   const float* __restrict__ mx,  const float* __restrict__ my,
                   const float* __restrict__ vsx, const float* __restrict__ asx,
                   const float* __restrict__ Rxp, const float* __restrict__ Ryp,
                   const float* __restrict__ Gx,  const float* __restrict__ Gy,
                   const float* __restrict__ WinW, const float* __restrict__ Winb,
                   const float* __restrict__ eWih, const float* __restrict__ eWhh,
                   const float* __restrict__ ebih, const float* __restrict__ ebhh,
                   const float* __restrict__ dWih, const float* __restrict__ dWhh,
                   const float* __restrict__ dbih, const float* __restrict__ dbhh,
                   const float* __restrict__ WoutW, const float* __restrict__ Woutb,
                   float* __restrict__ out)
{
    extern __shared__ char smraw[];
    SM& s = *reinterpret_cast<SM*>(smraw);
    const int tid  = threadIdx.x;
    const int b0   = blockIdx.x * BT;
    const int wid  = tid >> 5;
    const int lane = tid & 31;
    const int dg   = lane & 15;
    const int bq2  = lane >> 4;
    const int cb   = 16 * wid + 8 * bq2;   // dup-array column base for this thread's 4 batch

    // ---- one-time setup ----
    pack_weights(s, tid, eWih, eWhh, ebih, ebhh);
    for (int i = tid; i < 24 * 16; i += NTHR) {
        int k = i >> 4, dgi = i & 15;
        float2 v; v.x = WinW[dgi * 24 + k]; v.y = WinW[(dgi + 16) * 24 + k];
        s.Winp[k][dgi] = v;
    }
    if (tid < 16) { float2 v; v.x = Winb[tid]; v.y = Winb[tid + 16]; s.Winb2[tid] = v; }
    if (tid < 128) { int k = tid >> 2, q = tid & 3; s.WoutT[k][q] = WoutW[q * 32 + k]; }
    if (tid < 4)  s.Woutb[tid] = Woutb[tid];
    for (int i = tid; i < BT * 40; i += NTHR) {
        int b = i / 40, j = i % 40;
        s.Zs[j & 1][j >> 1][b] = hist[(size_t)(b0 + b) * 40 + j];
    }
    for (int i = tid; i < 3 * 32 * 128; i += NTHR)
        (&s.Hd[0][0][0])[i] = 0.f;

    const float rx = Rxp[0] * Rxp[0], ry = Ryp[0] * Ryp[0];
    const float vv = vsx[0] * vsx[0], aa = asx[0] * asx[0];
    const float gxe0 = Gx[0] * mx[0], gxe1 = Gx[1] * mx[0], gxe2 = Gx[2] * mx[0];
    const float gye0 = Gy[0] * my[0], gye1 = Gy[1] * my[0], gye2 = Gy[2] * my[0];
    const float gx0 = Gx[0], gx1 = Gx[1], gx2 = Gx[2];
    const float gy0 = Gy[0], gy1 = Gy[1], gy2 = Gy[2];

    if (tid < BT) {
        int b = tid;
#pragma unroll
        for (int j = 0; j < 24; j++) { s.XPd[j][2 * b] = 0.f; s.XPd[j][2 * b + 1] = 0.f; }
        float z0x = hist[(size_t)(b0 + b) * 40 + 0];
        float z0y = hist[(size_t)(b0 + b) * 40 + 1];
        s.XPd[0][2 * b] = z0x;  s.XPd[0][2 * b + 1] = z0x;
        s.XPd[3][2 * b] = z0y;  s.XPd[3][2 * b + 1] = z0y;
        // Px diag {rx, vv, aa}; Py diag same (ref uses R_x for both)
        s.XPd[6][2 * b] = rx;  s.XPd[6][2 * b + 1] = rx;
        s.XPd[10][2 * b] = vv; s.XPd[10][2 * b + 1] = vv;
        s.XPd[14][2 * b] = aa; s.XPd[14][2 * b + 1] = aa;
        s.XPd[15][2 * b] = rx; s.XPd[15][2 * b + 1] = rx;
        s.XPd[19][2 * b] = vv; s.XPd[19][2 * b + 1] = vv;
        s.XPd[23][2 * b] = aa; s.XPd[23][2 * b + 1] = aa;
    }

    float Creg[3][2][4];
#pragma unroll
    for (int l = 0; l < 3; l++)
#pragma unroll
        for (int dp = 0; dp < 2; dp++)
#pragma unroll
            for (int b = 0; b < 4; b++) Creg[l][dp][b] = 0.f;

    __syncthreads();

    // ---- encoder: t = 1..19 (warp-private) ----
    for (int t = 1; t < TH; t++) {
        run_stack(s, dg, cb, Creg);
        if (lane < 16) {
            int f = lane >> 3, bl = lane & 7;
            int b = 8 * wid + bl;
            int xo = f ? 3 : 0, po = f ? 15 : 6;
            float X[3], P[9];
#pragma unroll
            for (int i = 0; i < 3; i++) X[i] = s.XPd[xo + i][2 * b];
#pragma unroll
            for (int i = 0; i < 9; i++) P[i] = s.XPd[po + i][2 * b];
            if (f == 0) kpred_f(X, P, gxe0, gxe1, gxe2);
            else        kpred_f(X, P, gye0, gye1, gye2);
            kupd_f(X, P, s.Zs[f][t][b], f ? ry : rx);
#pragma unroll
            for (int i = 0; i < 3; i++) { s.XPd[xo + i][2 * b] = X[i]; s.XPd[xo + i][2 * b + 1] = X[i]; }
#pragma unroll
            for (int i = 0; i < 9; i++) { s.XPd[po + i][2 * b] = P[i]; s.XPd[po + i][2 * b + 1] = P[i]; }
        }
        __syncwarp();
    }

    // ---- swap in decoder weights (CTA-wide) ----
    __syncthreads();
    pack_weights(s, tid, dWih, dWhh, dbih, dbhh);
    __syncthreads();

    // ---- decoder: 30 steps (warp-private) ----
    for (int st = 0; st < LP; st++) {
        run_stack(s, dg, cb, Creg);
        // pred = c[2] @ Wout^T + b : each lane one (q, b) dot
        {
            int q = lane >> 3, bl = lane & 7;
            int b = 8 * wid + bl;
            float a = s.Woutb[q];
#pragma unroll 8
            for (int k = 0; k < 32; k++) a = fmaf(s.xd[k][2 * b], s.WoutT[k][q], a);
            s.pred[q][b] = a;
        }
        __syncwarp();
        if (lane < 16) {
            int f = lane >> 3, bl = lane & 7;
            int b = 8 * wid + bl;
            int xo = f ? 3 : 0, po = f ? 15 : 6;
            float X[3], P[9];
#pragma unroll
            for (int i = 0; i < 3; i++) X[i] = s.XPd[xo + i][2 * b];
#pragma unroll
            for (int i = 0; i < 9; i++) P[i] = s.XPd[po + i][2 * b];
            X[2] = DTC * s.pred[f][b];
            float sc = s.pred[2 + f][b];
            float q0 = sc * (f ? gy0 : gx0);
            float q1 = sc * (f ? gy1 : gx1);
            float q2 = sc * (f ? gy2 : gx2);
            kpred_f(X, P, q0, q1, q2);
#pragma unroll
            for (int i = 0; i < 3; i++) { s.XPd[xo + i][2 * b] = X[i]; s.XPd[xo + i][2 * b + 1] = X[i]; }
#pragma unroll
            for (int i = 0; i < 9; i++) { s.XPd[po + i][2 * b] = P[i]; s.XPd[po + i][2 * b + 1] = P[i]; }
            float* o = out + (size_t)(b0 + b) * (LP * 5) + st * 5;
            if (f == 0) { o[0] = X[0]; o[2] = sqrtf(P[0]); }
            else        { o[1] = X[0]; o[3] = sqrtf(P[0]); o[4] = 0.0f; }
        }
        __syncwarp();
    }
}

extern "C" void kernel_launch(void* const* d_in, const int* in_sizes, int n_in,
                              void* d_out, int out_size) {
    cudaFuncSetAttribute(kalman_lstm_kernel,
                         cudaFuncAttributeMaxDynamicSharedMemorySize,
                         (int)sizeof(SM));
    kalman_lstm_kernel<<<NCTA, NTHR, sizeof(SM)>>>(
        (const float*)d_in[0],  (const float*)d_in[1],  (const float*)d_in[2],
        (const float*)d_in[3],  (const float*)d_in[4],  (const float*)d_in[5],
        (const float*)d_in[6],  (const float*)d_in[7],  (const float*)d_in[8],
        (const float*)d_in[9],  (const float*)d_in[10], (const float*)d_in[11],
        (const float*)d_in[12], (const float*)d_in[13], (const float*)d_in[14],
        (const float*)d_in[15], (const float*)d_in[16], (const float*)d_in[17],
        (const float*)d_in[18], (const float*)d_in[19], (const float*)d_in[20],
        (float*)d_out);
}

// round 7
// speedup vs baseline: 1.3551x; 1.3551x over previous
#include <cuda_runtime.h>
#include <math.h>

#define BT   64
#define NCTA 128
#define NTHR 256
#define TH   20
#define LP   30
#define DTC  0.1f
#define D2C  0.005f

typedef unsigned long long ull;

struct SM {
    ulonglong2 Wp[3][64][32];   // 96KB: [l][k(0..31 x | 32..63 h)][d]: .x={Wi,Wf} .y={Wg,Wo}
    float  H[3][32][BT];        // 24KB
    float  xb[32][BT];          // 8KB  (input act / c of prev layer)
    float  XP[24][BT];          // 6KB  [Xx(3), Xy(3), Px(9), Py(9)]
    float  Zs[2][TH][BT];       // 10KB
    float  pred[4][BT];         // 1KB
    float4 bsum2[3][32];        // {bi,bf,bg,bo} per (l,d)
    float2 Winp[24][16];        // {Win[dg][k], Win[dg+16][k]}
    float2 Winb2[16];
    float  WoutT[32][4];
    float  Woutb[4];
};

__device__ __forceinline__ float tanha(float x) {
    float y; asm("tanh.approx.f32 %0, %1;" : "=f"(y) : "f"(x)); return y;
}
__device__ __forceinline__ float sigm(float z) {
    return fmaf(tanha(0.5f * z), 0.5f, 0.5f);
}
__device__ __forceinline__ void ffma2(ull& a, ull w, ull x) {
    asm("fma.rn.f32x2 %0, %1, %2, %0;" : "+l"(a) : "l"(w), "l"(x));
}
__device__ __forceinline__ float2 u2f2(ull v) {
    float2 r; asm("mov.b64 {%0, %1}, %2;" : "=f"(r.x), "=f"(r.y) : "l"(v)); return r;
}
__device__ __forceinline__ ull f2u2(float lo, float hi) {
    ull r; asm("mov.b64 %0, {%1, %2};" : "=l"(r) : "f"(lo), "f"(hi)); return r;
}
__device__ __forceinline__ ull dup(float v) {
    ull r; asm("mov.b64 %0, {%1, %1};" : "=l"(r) : "f"(v)); return r;
}

__device__ __forceinline__ void pack_weights(SM& s, int tid,
        const float* __restrict__ Wih, const float* __restrict__ Whh,
        const float* __restrict__ bih, const float* __restrict__ bhh) {
    for (int i = tid; i < 3 * 64 * 32; i += NTHR) {
        int d = i & 31, kk = (i >> 5) & 63, l = i >> 11;
        const float* W = (kk < 32) ? Wih : Whh;
        int k = kk & 31;
        int base = l * 4096 + d * 32 + k;
        float4 v;
        v.x = W[base];
        v.y = W[base + 1024];
        v.z = W[base + 2048];
        v.w = W[base + 3072];
        *reinterpret_cast<float4*>(&s.Wp[l][kk][d]) = v;
    }
    for (int i = tid; i < 96; i += NTHR) {
        int l = i >> 5, d = i & 31;
        int b = l * 128 + d;
        float4 v;
        v.x = bih[b]      + bhh[b];
        v.y = bih[b + 32] + bhh[b + 32];
        v.z = bih[b + 64] + bhh[b + 64];
        v.w = bih[b + 96] + bhh[b + 96];
        s.bsum2[l][d] = v;
    }
}

// Kalman predict with Q[i][j] = g_i * g_j
__device__ __forceinline__ void kpred_f(float X[3], float P[9],
                                        float g0, float g1, float g2) {
    X[0] = X[0] + DTC * X[1] + D2C * X[2];
    X[1] = X[1] + DTC * X[2];
    float A[9];
#pragma unroll
    for (int j = 0; j < 3; j++) {
        A[0 * 3 + j] = P[0 * 3 + j] + DTC * P[1 * 3 + j] + D2C * P[2 * 3 + j];
        A[1 * 3 + j] = P[1 * 3 + j] + DTC * P[2 * 3 + j];
        A[2 * 3 + j] = P[2 * 3 + j];
    }
#pragma unroll
    for (int i = 0; i < 3; i++) {
        float qi = (i == 0) ? g0 : ((i == 1) ? g1 : g2);
        P[i * 3 + 0] = A[i * 3 + 0] + DTC * A[i * 3 + 1] + D2C * A[i * 3 + 2] + qi * g0;
        P[i * 3 + 1] = A[i * 3 + 1] + DTC * A[i * 3 + 2] + qi * g1;
        P[i * 3 + 2] = A[i * 3 + 2] + qi * g2;
    }
}

__device__ __forceinline__ void kupd_f(float X[3], float P[9], float z, float R) {
    float y = z - X[0];
    float S = P[0] + R;
    float inv = 1.0f / S;
    float K0 = P[0] * inv, K1 = P[3] * inv, K2 = P[6] * inv;
    X[0] += y * K0; X[1] += y * K1; X[2] += y * K2;
    float r0 = P[0], r1 = P[1], r2 = P[2];
    P[0] -= K0 * r0; P[1] -= K0 * r1; P[2] -= K0 * r2;
    P[3] -= K1 * r0; P[4] -= K1 * r1; P[5] -= K1 * r2;
    P[6] -= K2 * r0; P[7] -= K2 * r1; P[8] -= K2 * r2;
}

// input layer + 3 LSTM layers; leaves c[2] in s.xb. Ends with __syncthreads().
__device__ __forceinline__ void run_stack(SM& s, int bq, int dg, float Creg[3][2][4]) {
    // ---- input layer: x = tanh(XP @ Win^T + b), paired over (dg, dg+16) ----
    {
        float2 wb = s.Winb2[dg];
        ull binit = f2u2(wb.x, wb.y);
        ull acc[4];
#pragma unroll
        for (int b = 0; b < 4; b++) acc[b] = binit;
#pragma unroll 4
        for (int k = 0; k < 24; k++) {
            float4 xv = *(const float4*)&s.XP[k][bq * 4];
            ull w = *(const ull*)&s.Winp[k][dg];
            ffma2(acc[0], w, dup(xv.x));
            ffma2(acc[1], w, dup(xv.y));
            ffma2(acc[2], w, dup(xv.z));
            ffma2(acc[3], w, dup(xv.w));
        }
        float4 r0, r1;
        float2 v0 = u2f2(acc[0]), v1 = u2f2(acc[1]), v2 = u2f2(acc[2]), v3 = u2f2(acc[3]);
        r0.x = tanha(v0.x); r0.y = tanha(v1.x); r0.z = tanha(v2.x); r0.w = tanha(v3.x);
        r1.x = tanha(v0.y); r1.y = tanha(v1.y); r1.z = tanha(v2.y); r1.w = tanha(v3.y);
        *(float4*)&s.xb[dg][bq * 4]      = r0;
        *(float4*)&s.xb[dg + 16][bq * 4] = r1;
    }
    __syncthreads();

    // ---- 3 LSTM layers: accs paired over gates {i,f} and {g,o} ----
#pragma unroll 1
    for (int l = 0; l < 3; l++) {
        float4 b0 = s.bsum2[l][dg];
        float4 b1 = s.bsum2[l][dg + 16];
        ull aif[2][4], ago[2][4];
        {
            ull i0 = f2u2(b0.x, b0.y), g0 = f2u2(b0.z, b0.w);
            ull i1 = f2u2(b1.x, b1.y), g1 = f2u2(b1.z, b1.w);
#pragma unroll
            for (int b = 0; b < 4; b++) {
                aif[0][b] = i0; ago[0][b] = g0;
                aif[1][b] = i1; ago[1][b] = g1;
            }
        }
        const ulonglong2* __restrict__ wl = &s.Wp[l][0][0];
        // x part
#pragma unroll 4
        for (int k = 0; k < 32; k++) {
            float4 xv = *(const float4*)&s.xb[k][bq * 4];
            ulonglong2 w0 = wl[k * 32 + dg];
            ulonglong2 w1 = wl[k * 32 + dg + 16];
            ull x0 = dup(xv.x), x1 = dup(xv.y), x2 = dup(xv.z), x3 = dup(xv.w);
            ffma2(aif[0][0], w0.x, x0); ffma2(ago[0][0], w0.y, x0);
            ffma2(aif[0][1], w0.x, x1); ffma2(ago[0][1], w0.y, x1);
            ffma2(aif[0][2], w0.x, x2); ffma2(ago[0][2], w0.y, x2);
            ffma2(aif[0][3], w0.x, x3); ffma2(ago[0][3], w0.y, x3);
            ffma2(aif[1][0], w1.x, x0); ffma2(ago[1][0], w1.y, x0);
            ffma2(aif[1][1], w1.x, x1); ffma2(ago[1][1], w1.y, x1);
            ffma2(aif[1][2], w1.x, x2); ffma2(ago[1][2], w1.y, x2);
            ffma2(aif[1][3], w1.x, x3); ffma2(ago[1][3], w1.y, x3);
        }
        // h part
        const float* __restrict__ hl = &s.H[l][0][0];
#pragma unroll 4
        for (int k = 0; k < 32; k++) {
            float4 hv = *(const float4*)&hl[k * BT + bq * 4];
            ulonglong2 w0 = wl[(32 + k) * 32 + dg];
            ulonglong2 w1 = wl[(32 + k) * 32 + dg + 16];
            ull x0 = dup(hv.x), x1 = dup(hv.y), x2 = dup(hv.z), x3 = dup(hv.w);
            ffma2(aif[0][0], w0.x, x0); ffma2(ago[0][0], w0.y, x0);
            ffma2(aif[0][1], w0.x, x1); ffma2(ago[0][1], w0.y, x1);
            ffma2(aif[0][2], w0.x, x2); ffma2(ago[0][2], w0.y, x2);
            ffma2(aif[0][3], w0.x, x3); ffma2(ago[0][3], w0.y, x3);
            ffma2(aif[1][0], w1.x, x0); ffma2(ago[1][0], w1.y, x0);
            ffma2(aif[1][1], w1.x, x1); ffma2(ago[1][1], w1.y, x1);
            ffma2(aif[1][2], w1.x, x2); ffma2(ago[1][2], w1.y, x2);
            ffma2(aif[1][3], w1.x, x3); ffma2(ago[1][3], w1.y, x3);
        }
        __syncthreads();  // all reads of xb / H[l] complete before overwrite
#pragma unroll
        for (int dp = 0; dp < 2; dp++) {
            int d = dg + 16 * dp;
            float cn[4], hn[4];
#pragma unroll
            for (int b = 0; b < 4; b++) {
                float2 vif = u2f2(aif[dp][b]);
                float2 vgo = u2f2(ago[dp][b]);
                float c = fmaf(sigm(vif.y), Creg[l][dp][b], sigm(vif.x) * tanha(vgo.x));
                float h = sigm(vgo.y) * tanha(c);
                Creg[l][dp][b] = c;
                cn[b] = c; hn[b] = h;
            }
            float4 cv, hv;
            cv.x = cn[0]; cv.y = cn[1]; cv.z = cn[2]; cv.w = cn[3];
            hv.x = hn[0]; hv.y = hn[1]; hv.z = hn[2]; hv.w = hn[3];
            *(float4*)&s.xb[d][bq * 4]     = cv;
            *(float4*)&s.H[l][d][bq * 4]   = hv;
        }
        __syncthreads();
    }
}

__global__ void __launch_bounds__(NTHR, 1)
kalman_lstm_kernel(const float* __restrict__ hist,
                   const float* __restrict__ mx,  const float* __restrict__ my,
                   const float* __restrict__ vsx, const float* __restrict__ asx,
                   const float* __restrict__ Rxp, const float* __restrict__ Ryp,
                   const float* __restrict__ Gx,  const float* __restrict__ Gy,
                   const float* __restrict__ WinW, const float* __restrict__ Winb,
                   const float* __restrict__ eWih, const float* __restrict__ eWhh,
                   const float* __restrict__ ebih, const float* __restrict__ ebhh,
                   const float* __restrict__ dWih, const float* __restrict__ dWhh,
                   const float* __restrict__ dbih, const float* __restrict__ dbhh,
                   const float* __restrict__ WoutW, const float* __restrict__ Woutb,
                   float* __restrict__ out)
{
    extern __shared__ char smraw[];
    SM& s = *reinterpret_cast<SM*>(smraw);
    const int tid = threadIdx.x;
    const int b0  = blockIdx.x * BT;
    const int bq  = tid & 15;
    const int dg  = tid >> 4;

    // ---- one-time setup ----
    pack_weights(s, tid, eWih, eWhh, ebih, ebhh);
    for (int i = tid; i < 24 * 16; i += NTHR) {
        int k = i >> 4, dgi = i & 15;
        float2 v; v.x = WinW[dgi * 24 + k]; v.y = WinW[(dgi + 16) * 24 + k];
        s.Winp[k][dgi] = v;
    }
    if (tid < 16) { float2 v; v.x = Winb[tid]; v.y = Winb[tid + 16]; s.Winb2[tid] = v; }
    if (tid < 128) { int k = tid >> 2, q = tid & 3; s.WoutT[k][q] = WoutW[q * 32 + k]; }
    if (tid < 4)  s.Woutb[tid] = Woutb[tid];
    for (int i = tid; i < BT * 40; i += NTHR) {
        int b = i / 40, j = i % 40;
        s.Zs[j & 1][j >> 1][b] = hist[(size_t)(b0 + b) * 40 + j];
    }
    for (int i = tid; i < 3 * 32 * BT; i += NTHR)
        (&s.H[0][0][0])[i] = 0.f;

    const float rx = Rxp[0] * Rxp[0], ry = Ryp[0] * Ryp[0];
    const float vv = vsx[0] * vsx[0], aa = asx[0] * asx[0];
    const float gxe0 = Gx[0] * mx[0], gxe1 = Gx[1] * mx[0], gxe2 = Gx[2] * mx[0];
    const float gye0 = Gy[0] * my[0], gye1 = Gy[1] * my[0], gye2 = Gy[2] * my[0];
    const float gx0 = Gx[0], gx1 = Gx[1], gx2 = Gx[2];
    const float gy0 = Gy[0], gy1 = Gy[1], gy2 = Gy[2];

    if (tid < BT) {
        int b = tid;
#pragma unroll
        for (int j = 0; j < 24; j++) s.XP[j][b] = 0.f;
        s.XP[0][b]  = hist[(size_t)(b0 + b) * 40 + 0];
        s.XP[3][b]  = hist[(size_t)(b0 + b) * 40 + 1];
        s.XP[6][b]  = rx; s.XP[10][b] = vv; s.XP[14][b] = aa;   // Px diag
        s.XP[15][b] = rx; s.XP[19][b] = vv; s.XP[23][b] = aa;   // Py diag (ref uses R_x too)
    }

    float Creg[3][2][4];
#pragma unroll
    for (int l = 0; l < 3; l++)
#pragma unroll
        for (int dp = 0; dp < 2; dp++)
#pragma unroll
            for (int b = 0; b < 4; b++) Creg[l][dp][b] = 0.f;

    __syncthreads();

    // ---- encoder: t = 1..19 ----
    for (int t = 1; t < TH; t++) {
        run_stack(s, bq, dg, Creg);
        if (tid < 128) {
            int b = tid & 63, f = tid >> 6;
            int xo = f ? 3 : 0, po = f ? 15 : 6;
            float X[3], P[9];
#pragma unroll
            for (int i = 0; i < 3; i++) X[i] = s.XP[xo + i][b];
#pragma unroll
            for (int i = 0; i < 9; i++) P[i] = s.XP[po + i][b];
            if (f == 0) kpred_f(X, P, gxe0, gxe1, gxe2);
            else        kpred_f(X, P, gye0, gye1, gye2);
            kupd_f(X, P, s.Zs[f][t][b], f ? ry : rx);
#pragma unroll
            for (int i = 0; i < 3; i++) s.XP[xo + i][b] = X[i];
#pragma unroll
            for (int i = 0; i < 9; i++) s.XP[po + i][b] = P[i];
        }
        __syncthreads();
    }

    // ---- swap in decoder weights ----
    pack_weights(s, tid, dWih, dWhh, dbih, dbhh);
    __syncthreads();

    // ---- decoder: 30 steps ----
    for (int st = 0; st < LP; st++) {
        run_stack(s, bq, dg, Creg);
        // pred = c[2] @ Wout^T + b : 256 threads, one (q,b) dot each
        {
            int q = tid >> 6, b = tid & 63;
            float a = s.Woutb[q];
#pragma unroll 8
            for (int k = 0; k < 32; k++) a = fmaf(s.xb[k][b], s.WoutT[k][q], a);
            s.pred[q][b] = a;
        }
        __syncthreads();
        if (tid < 128) {
            int b = tid & 63, f = tid >> 6;
            int xo = f ? 3 : 0, po = f ? 15 : 6;
            float X[3], P[9];
#pragma unroll
            for (int i = 0; i < 3; i++) X[i] = s.XP[xo + i][b];
#pragma unroll
            for (int i = 0; i < 9; i++) P[i] = s.XP[po + i][b];
            X[2] = DTC * s.pred[f][b];
            float sc = s.pred[2 + f][b];
            float q0 = sc * (f ? gy0 : gx0);
            float q1 = sc * (f ? gy1 : gx1);
            float q2 = sc * (f ? gy2 : gx2);
            kpred_f(X, P, q0, q1, q2);
#pragma unroll
            for (int i = 0; i < 3; i++) s.XP[xo + i][b] = X[i];
#pragma unroll
            for (int i = 0; i < 9; i++) s.XP[po + i][b] = P[i];
            float* o = out + (size_t)(b0 + b) * (LP * 5) + st * 5;
            if (f == 0) { o[0] = X[0]; o[2] = sqrtf(P[0]); }
            else        { o[1] = X[0]; o[3] = sqrtf(P[0]); o[4] = 0.0f; }
        }
        __syncthreads();
    }
}

extern "C" void kernel_launch(void* const* d_in, const int* in_sizes, int n_in,
                              void* d_out, int out_size) {
    cudaFuncSetAttribute(kalman_lstm_kernel,
                         cudaFuncAttributeMaxDynamicSharedMemorySize,
                         (int)sizeof(SM));
    kalman_lstm_kernel<<<NCTA, NTHR, sizeof(SM)>>>(
        (const float*)d_in[0],  (const float*)d_in[1],  (const float*)d_in[2],
        (const float*)d_in[3],  (const float*)d_in[4],  (const float*)d_in[5],
        (const float*)d_in[6],  (const float*)d_in[7],  (const float*)d_in[8],
        (const float*)d_in[9],  (const float*)d_in[10], (const float*)d_in[11],
        (const float*)d_in[12], (const float*)d_in[13], (const float*)d_in[14],
        (const float*)d_in[15], (const float*)d_in[16], (const float*)d_in[17],
        (const float*)d_in[18], (const float*)d_in[19], (const float*)d_in[20],
        (float*)d_out);
}